// round 11
// baseline (speedup 1.0000x reference)
#include <cuda_runtime.h>
#include <math.h>
#include <stdint.h>

#define NTOK 8192
#define DM   512
#define NE   8
#define TOPK 2
#define NASSIGN (NTOK * TOPK)

// ---------------- scratch (device globals: no allocation allowed) ----------------
__device__ int      g_count[NE];
__device__ int      g_offs[NE];
__device__ int      g_cursor[NE];
__device__ int      g_eidx[NTOK][TOPK];
__device__ float    g_gate[NTOK][TOPK];
__device__ int      g_tok[NASSIGN];
__device__ int      g_slot[NTOK][TOPK];
__device__ float    g_y[(size_t)NASSIGN * DM];      // 32 MB expert-output scratch
__device__ unsigned g_wt[(size_t)NE * DM * DM];     // 8 MB: W^T tf32 bits [e][n][k]
__device__ unsigned g_xt[(size_t)NTOK * DM];        // 16 MB: x tf32 bits [tok][k]

// ---------------- helpers ----------------
__device__ __forceinline__ unsigned f2tf32(float f) {
    unsigned u;
    asm("cvt.rna.tf32.f32 %0, %1;" : "=r"(u) : "f"(f));
    return u;
}
__device__ __forceinline__ uint32_t smem_u32(const void* p) {
    uint32_t a;
    asm("{ .reg .u64 t; cvta.to.shared.u64 t, %1; cvt.u32.u64 %0, t; }" : "=r"(a) : "l"(p));
    return a;
}
__device__ __forceinline__ void cp16(uint32_t dst, const void* src) {
    asm volatile("cp.async.cg.shared.global [%0], [%1], 16;" :: "r"(dst), "l"(src));
}
#define CP_COMMIT() asm volatile("cp.async.commit_group;" ::: "memory")
#define CP_WAIT1()  asm volatile("cp.async.wait_group 1;" ::: "memory")

__device__ __forceinline__ void mma_tf32(float d[4], const unsigned a[4], const unsigned b[2]) {
    asm volatile(
        "mma.sync.aligned.m16n8k8.row.col.f32.tf32.tf32.f32 "
        "{%0,%1,%2,%3}, {%4,%5,%6,%7}, {%8,%9}, {%0,%1,%2,%3};"
        : "+f"(d[0]), "+f"(d[1]), "+f"(d[2]), "+f"(d[3])
        : "r"(a[0]), "r"(a[1]), "r"(a[2]), "r"(a[3]), "r"(b[0]), "r"(b[1]));
}

// ---------------- 0: W^T + tf32 convert (also resets counters) ----------------
__global__ void wtrans_kernel(const float* __restrict__ ew) {
    __shared__ float t[32][33];
    int e  = blockIdx.z;
    int k0 = blockIdx.x * 32, n0 = blockIdx.y * 32;
    int tx = threadIdx.x, ty = threadIdx.y;      // (32, 8)
    if (blockIdx.x == 0 && blockIdx.y == 0 && blockIdx.z == 0 && ty == 0 && tx < NE)
        g_count[tx] = 0;
    const float* src = ew + (size_t)e * DM * DM;
#pragma unroll
    for (int j = 0; j < 32; j += 8)
        t[ty + j][tx] = src[(size_t)(k0 + ty + j) * DM + n0 + tx];
    __syncthreads();
    unsigned* dst = g_wt + (size_t)e * DM * DM;
#pragma unroll
    for (int j = 0; j < 32; j += 8)
        dst[(size_t)(n0 + ty + j) * DM + k0 + tx] = f2tf32(t[tx][ty + j]);
}

// ---------------- 1: gating (warp per token) + x -> tf32 conversion ----------------
__global__ void gate_kernel(const float* __restrict__ x,
                            const float* __restrict__ wg) {
    __shared__ float sw[DM * NE];                 // 16 KB: w_gate [d][e]
    int tid = threadIdx.x;                        // 256
    for (int i = tid; i < DM * NE; i += 256) sw[i] = wg[i];
    __syncthreads();

    int warp = tid >> 5, lane = tid & 31;
    int token = blockIdx.x * 8 + warp;

    const float4* xr4 = (const float4*)(x + (size_t)token * DM);
    uint4* xt4 = (uint4*)(g_xt + (size_t)token * DM);

    float acc[NE];
#pragma unroll
    for (int e = 0; e < NE; e++) acc[e] = 0.f;

#pragma unroll
    for (int i = 0; i < 4; i++) {
        int q = lane + i * 32;                    // float4 index within row
        float4 v = xr4[q];
        int d = q * 4;
        const float* w0 = &sw[(d + 0) * NE];
        const float* w1 = &sw[(d + 1) * NE];
        const float* w2 = &sw[(d + 2) * NE];
        const float* w3 = &sw[(d + 3) * NE];
#pragma unroll
        for (int e = 0; e < NE; e++)
            acc[e] += v.x * w0[e] + v.y * w1[e] + v.z * w2[e] + v.w * w3[e];
        uint4 u;
        u.x = f2tf32(v.x); u.y = f2tf32(v.y); u.z = f2tf32(v.z); u.w = f2tf32(v.w);
        xt4[q] = u;
    }
#pragma unroll
    for (int e = 0; e < NE; e++) {
#pragma unroll
        for (int off = 16; off > 0; off >>= 1)
            acc[e] += __shfl_xor_sync(0xFFFFFFFFu, acc[e], off);
    }
    if (lane == 0) {
        int i0 = 0; float v0 = acc[0];
#pragma unroll
        for (int e = 1; e < NE; e++) if (acc[e] > v0) { v0 = acc[e]; i0 = e; }
        int i1 = -1; float v1 = -3.0e38f;
#pragma unroll
        for (int e = 0; e < NE; e++) if (e != i0 && acc[e] > v1) { v1 = acc[e]; i1 = e; }
        float e1 = expf(v1 - v0);
        float inv = 1.f / (1.f + e1);
        g_eidx[token][0] = i0;  g_eidx[token][1] = i1;
        g_gate[token][0] = inv; g_gate[token][1] = e1 * inv;
        atomicAdd(&g_count[i0], 1);
        atomicAdd(&g_count[i1], 1);
    }
}

// ---------------- 2: tiny exclusive scan ----------------
__global__ void scan_kernel() {
    if (threadIdx.x == 0) {
        int acc = 0;
        for (int e = 0; e < NE; e++) {
            g_offs[e] = acc; g_cursor[e] = acc; acc += g_count[e];
        }
    }
}

// ---------------- 3: slot assignment (block-aggregated atomics) ----------------
__global__ void assign_kernel() {
    __shared__ int loc[NE], bbase[NE];
    int tid = threadIdx.x;
    if (tid < NE) loc[tid] = 0;
    __syncthreads();
    int n = blockIdx.x * 256 + tid;
    int e[TOPK], p[TOPK];
#pragma unroll
    for (int k = 0; k < TOPK; k++) {
        e[k] = g_eidx[n][k];
        p[k] = atomicAdd(&loc[e[k]], 1);
    }
    __syncthreads();
    if (tid < NE) bbase[tid] = atomicAdd(&g_cursor[tid], loc[tid]);
    __syncthreads();
#pragma unroll
    for (int k = 0; k < TOPK; k++) {
        int pos = bbase[e[k]] + p[k];
        g_tok[pos]   = n;
        g_slot[n][k] = pos;
    }
}

// ---------------- 4: grouped expert GEMM, tf32 mma.sync + 3-stage cp.async ----------------
// CTA tile 128x128, k-tile 32, warps 2x4 (warp tile 64x32). Both operands pre-converted
// tf32 bits: A = g_xt gathered rows, B = g_wt (W^T, [n][k]) -> both tiles are
// [128 rows][32 k-words] with row stride 36 words (144 B, 16B-aligned, conflict-free).
#define KTILE    32
#define LDW      36
#define ROW_B    (LDW * 4)              // 144 bytes
#define AB_BYTES (128 * ROW_B)          // 18432 per operand
#define STAGE_B  (2 * AB_BYTES)         // 36864 per stage
#define STAGES   3
#define DYN_SMEM (STAGES * STAGE_B)     // 110592

__global__ void __launch_bounds__(256, 2)
expert_gemm() {
    const int e   = blockIdx.z;
    const int cnt = g_count[e];
    const int m0  = blockIdx.y * 128;
    if (m0 >= cnt) return;
    const int n0   = blockIdx.x * 128;
    const int base = g_offs[e];

    extern __shared__ __align__(16) char dyn[];
    const uint32_t sbase = smem_u32(dyn);

    const int tid  = threadIdx.x;   // 256
    const int lane = tid & 31;
    const int wid  = tid >> 5;
    const int wm   = (wid & 1) * 64;
    const int wn   = (wid >> 1) * 32;
    const int gr   = lane >> 2;
    const int gc   = lane & 3;

    // ---- cp.async mapping: row = tid>>1 (0..127), half = tid&1 (64B each) ----
    const int row    = tid >> 1;
    const int half64 = (tid & 1) * 64;
    int rr = m0 + row; if (rr >= cnt) rr = cnt - 1;     // clamp; rows >= cnt never stored
    const char* arow = (const char*)(g_xt + (size_t)g_tok[base + rr] * DM) + half64;
    const char* brow = (const char*)(g_wt + ((size_t)e * DM + n0 + row) * DM) + half64;
    const uint32_t dst_off = (uint32_t)(row * ROW_B + half64);

#define ISSUE_STAGE(buf, kt) do {                                   \
    uint32_t _ad = sbase + (uint32_t)(buf) * STAGE_B + dst_off;     \
    const char* _as = arow + (kt) * (KTILE * 4);                    \
    const char* _bs = brow + (kt) * (KTILE * 4);                    \
    cp16(_ad,                 _as);      cp16(_ad + 16,            _as + 16); \
    cp16(_ad + 32,            _as + 32); cp16(_ad + 48,            _as + 48); \
    cp16(_ad + AB_BYTES,      _bs);      cp16(_ad + AB_BYTES + 16, _bs + 16); \
    cp16(_ad + AB_BYTES + 32, _bs + 32); cp16(_ad + AB_BYTES + 48, _bs + 48); \
} while (0)

    float acc[4][4][4];
#pragma unroll
    for (int mi = 0; mi < 4; mi++)
#pragma unroll
        for (int ni = 0; ni < 4; ni++)
#pragma unroll
            for (int q = 0; q < 4; q++) acc[mi][ni][q] = 0.f;

    // ---- prologue: stages 0,1 ----
    ISSUE_STAGE(0, 0); CP_COMMIT();
    ISSUE_STAGE(1, 1); CP_COMMIT();

    const int NKT = DM / KTILE;     // 16
    for (int kt = 0; kt < NKT; kt++) {
        CP_WAIT1();                 // stage kt arrived
        __syncthreads();            // visible to all; prior compute (kt-1) done

        // issue stage kt+2 into buffer (kt+2)%3 (== buffer of kt-1, now free)
        if (kt + STAGES - 1 < NKT) ISSUE_STAGE((kt + 2) % STAGES, kt + 2);
        CP_COMMIT();                // always commit (empty groups keep count aligned)

        const unsigned* Ab = (const unsigned*)(dyn + (kt % STAGES) * STAGE_B);
        const unsigned* Bb = (const unsigned*)(dyn + (kt % STAGES) * STAGE_B + AB_BYTES);

#pragma unroll
        for (int s = 0; s < 4; s++) {
            const int kb = s * 8;
            unsigned a[4][4], b[4][2];
#pragma unroll
            for (int mi = 0; mi < 4; mi++) {
                const unsigned* r0 = Ab + (wm + mi * 16 + gr) * LDW;
                const unsigned* r1 = r0 + 8 * LDW;
                a[mi][0] = r0[kb + gc];
                a[mi][1] = r1[kb + gc];
                a[mi][2] = r0[kb + gc + 4];
                a[mi][3] = r1[kb + gc + 4];
            }
#pragma unroll
            for (int ni = 0; ni < 4; ni++) {
                const unsigned* rb = Bb + (wn + ni * 8 + gr) * LDW;
                b[ni][0] = rb[kb + gc];
                b[ni][1] = rb[kb + gc + 4];
            }
#pragma unroll
            for (int mi = 0; mi < 4; mi++)
#pragma unroll
                for (int ni = 0; ni < 4; ni++)
                    mma_tf32(acc[mi][ni], a[mi], b[ni]);
        }
    }

    // ---- epilogue: d0/d1 -> (row, 2c), d2/d3 -> (row+8, 2c) ----
#pragma unroll
    for (int mi = 0; mi < 4; mi++) {
        int r0 = m0 + wm + mi * 16 + gr;
        int r1 = r0 + 8;
#pragma unroll
        for (int ni = 0; ni < 4; ni++) {
            int c = n0 + wn + ni * 8 + 2 * gc;
            if (r0 < cnt)
                *(float2*)(g_y + (size_t)(base + r0) * DM + c) =
                    make_float2(acc[mi][ni][0], acc[mi][ni][1]);
            if (r1 < cnt)
                *(float2*)(g_y + (size_t)(base + r1) * DM + c) =
                    make_float2(acc[mi][ni][2], acc[mi][ni][3]);
        }
    }
#undef ISSUE_STAGE
}

// ---------------- 5: log-domain combine (flat grid, fast intrinsics) ----------------
__device__ __forceinline__ float comb1(float g0, float g1, float ya, float yb) {
    float c = g0 * __expf(ya) + g1 * __expf(yb);
    if (c == 0.f) c = 2.220446049250313e-16f;
    return __logf(c);
}
__global__ void combine_kernel(float* __restrict__ out) {
    int idx = blockIdx.x * 256 + threadIdx.x;     // float4 granularity
    int n = idx >> 7, f = idx & 127;
    float g0 = g_gate[n][0], g1 = g_gate[n][1];
    const float4* y0 = (const float4*)(g_y + (size_t)g_slot[n][0] * DM);
    const float4* y1 = (const float4*)(g_y + (size_t)g_slot[n][1] * DM);
    float4 a = y0[f], b = y1[f];
    float4 rv;
    rv.x = comb1(g0, g1, a.x, b.x);
    rv.y = comb1(g0, g1, a.y, b.y);
    rv.z = comb1(g0, g1, a.z, b.z);
    rv.w = comb1(g0, g1, a.w, b.w);
    ((float4*)(out + (size_t)n * DM))[f] = rv;
}

// ---------------- 6: balance loss (deterministic reduction) ----------------
__global__ void loss_kernel(float* __restrict__ out, int out_size) {
    __shared__ float s[NE][256];
    int tid = threadIdx.x;
    float imp[NE];
#pragma unroll
    for (int e = 0; e < NE; e++) imp[e] = 0.f;
    for (int n = tid; n < NTOK; n += 256) {
#pragma unroll
        for (int k = 0; k < TOPK; k++)
            imp[g_eidx[n][k]] += g_gate[n][k];
    }
#pragma unroll
    for (int e = 0; e < NE; e++) s[e][tid] = imp[e];
    __syncthreads();
    for (int st = 128; st > 0; st >>= 1) {
        if (tid < st) {
#pragma unroll
            for (int e = 0; e < NE; e++) s[e][tid] += s[e][tid + st];
        }
        __syncthreads();
    }
    if (tid == 0) {
        float mi = 0.f, ml = 0.f, iv[NE], lv[NE];
        for (int e = 0; e < NE; e++) {
            iv[e] = s[e][0]; lv[e] = (float)g_count[e];
            mi += iv[e]; ml += lv[e];
        }
        mi *= (1.f / NE); ml *= (1.f / NE);
        float vi = 0.f, vl = 0.f;
        for (int e = 0; e < NE; e++) {
            float di = iv[e] - mi, dl = lv[e] - ml;
            vi += di * di; vl += dl * dl;
        }
        vi *= (1.f / NE); vl *= (1.f / NE);
        float loss = vi / (mi * mi + 1e-10f) + vl / (ml * ml + 1e-10f);
        if (out_size > NTOK * DM) out[NTOK * DM] = loss;
    }
}

// ---------------- launch ----------------
extern "C" void kernel_launch(void* const* d_in, const int* in_sizes, int n_in,
                              void* d_out, int out_size) {
    const float* x  = (const float*)d_in[0];   // [8192, 512]
    const float* wg = (const float*)d_in[1];   // [512, 8]
    const float* ew = (const float*)d_in[2];   // [8, 512, 512]
    float* out = (float*)d_out;

    static int attr_done = 0;
    if (!attr_done) {
        cudaFuncSetAttribute(expert_gemm, cudaFuncAttributeMaxDynamicSharedMemorySize, DYN_SMEM);
        attr_done = 1;
    }

    {
        dim3 g(DM / 32, DM / 32, NE);
        wtrans_kernel<<<g, dim3(32, 8)>>>(ew);      // also resets g_count
    }
    gate_kernel<<<NTOK / 8, 256>>>(x, wg);          // also writes g_xt (tf32 bits)
    scan_kernel<<<1, 32>>>();
    assign_kernel<<<NTOK / 256, 256>>>();
    {
        dim3 grid(DM / 128, NTOK / 128, NE);
        expert_gemm<<<grid, 256, DYN_SMEM>>>();
    }
    combine_kernel<<<NTOK * (DM / 4) / 256, 256>>>(out);
    loss_kernel<<<1, 256>>>(out, out_size);
}

// round 12
// speedup vs baseline: 1.0393x; 1.0393x over previous
#include <cuda_runtime.h>
#include <math.h>
#include <stdint.h>

#define NTOK 8192
#define DM   512
#define NE   8
#define TOPK 2
#define NASSIGN (NTOK * TOPK)

// ---------------- scratch (device globals: no allocation allowed) ----------------
__device__ int      g_count[NE];
__device__ int      g_offs[NE];
__device__ int      g_cursor[NE];
__device__ int      g_done;                         // zero-init; reset after use
__device__ int      g_eidx[NTOK][TOPK];
__device__ float    g_gate[NTOK][TOPK];
__device__ int      g_tok[NASSIGN];
__device__ int      g_slot[NTOK][TOPK];
__device__ float    g_y[(size_t)NASSIGN * DM];      // 32 MB expert-output scratch
__device__ unsigned g_wt[(size_t)NE * DM * DM];     // 8 MB: W^T tf32 bits [e][n][k]
__device__ unsigned g_xt[(size_t)NTOK * DM];        // 16 MB: x tf32 bits [tok][k]

// ---------------- helpers ----------------
__device__ __forceinline__ unsigned f2tf32(float f) {
    unsigned u;
    asm("cvt.rna.tf32.f32 %0, %1;" : "=r"(u) : "f"(f));
    return u;
}
__device__ __forceinline__ void mma_tf32(float d[4], const unsigned a[4], const unsigned b[2]) {
    asm volatile(
        "mma.sync.aligned.m16n8k8.row.col.f32.tf32.tf32.f32 "
        "{%0,%1,%2,%3}, {%4,%5,%6,%7}, {%8,%9}, {%0,%1,%2,%3};"
        : "+f"(d[0]), "+f"(d[1]), "+f"(d[2]), "+f"(d[3])
        : "r"(a[0]), "r"(a[1]), "r"(a[2]), "r"(a[3]), "r"(b[0]), "r"(b[1]));
}

// ---------------- 0: W^T + tf32 convert (also resets counters) ----------------
__global__ void wtrans_kernel(const float* __restrict__ ew) {
    __shared__ float t[32][33];
    int e  = blockIdx.z;
    int k0 = blockIdx.x * 32, n0 = blockIdx.y * 32;
    int tx = threadIdx.x, ty = threadIdx.y;      // (32, 8)
    if (blockIdx.x == 0 && blockIdx.y == 0 && blockIdx.z == 0 && ty == 0 && tx < NE)
        g_count[tx] = 0;
    const float* src = ew + (size_t)e * DM * DM;
#pragma unroll
    for (int j = 0; j < 32; j += 8)
        t[ty + j][tx] = src[(size_t)(k0 + ty + j) * DM + n0 + tx];
    __syncthreads();
    unsigned* dst = g_wt + (size_t)e * DM * DM;
#pragma unroll
    for (int j = 0; j < 32; j += 8)
        dst[(size_t)(n0 + ty + j) * DM + k0 + tx] = f2tf32(t[tx][ty + j]);
}

// ---------------- 1: gating (warp per token) + x->tf32 + last-block scan ----------------
__global__ void gate_kernel(const float* __restrict__ x,
                            const float* __restrict__ wg) {
    __shared__ float sw[DM * NE];                 // 16 KB: w_gate [d][e]
    int tid = threadIdx.x;                        // 256
    for (int i = tid; i < DM * NE; i += 256) sw[i] = wg[i];
    __syncthreads();

    int warp = tid >> 5, lane = tid & 31;
    int token = blockIdx.x * 8 + warp;

    const float4* xr4 = (const float4*)(x + (size_t)token * DM);
    uint4* xt4 = (uint4*)(g_xt + (size_t)token * DM);

    float acc[NE];
#pragma unroll
    for (int e = 0; e < NE; e++) acc[e] = 0.f;

#pragma unroll
    for (int i = 0; i < 4; i++) {
        int q = lane + i * 32;                    // float4 index within row
        float4 v = xr4[q];
        int d = q * 4;
        const float* w0 = &sw[(d + 0) * NE];
        const float* w1 = &sw[(d + 1) * NE];
        const float* w2 = &sw[(d + 2) * NE];
        const float* w3 = &sw[(d + 3) * NE];
#pragma unroll
        for (int e = 0; e < NE; e++)
            acc[e] += v.x * w0[e] + v.y * w1[e] + v.z * w2[e] + v.w * w3[e];
        uint4 u;
        u.x = f2tf32(v.x); u.y = f2tf32(v.y); u.z = f2tf32(v.z); u.w = f2tf32(v.w);
        xt4[q] = u;
    }
#pragma unroll
    for (int e = 0; e < NE; e++) {
#pragma unroll
        for (int off = 16; off > 0; off >>= 1)
            acc[e] += __shfl_xor_sync(0xFFFFFFFFu, acc[e], off);
    }
    if (lane == 0) {
        int i0 = 0; float v0 = acc[0];
#pragma unroll
        for (int e = 1; e < NE; e++) if (acc[e] > v0) { v0 = acc[e]; i0 = e; }
        int i1 = -1; float v1 = -3.0e38f;
#pragma unroll
        for (int e = 0; e < NE; e++) if (e != i0 && acc[e] > v1) { v1 = acc[e]; i1 = e; }
        float e1 = expf(v1 - v0);
        float inv = 1.f / (1.f + e1);
        g_eidx[token][0] = i0;  g_eidx[token][1] = i1;
        g_gate[token][0] = inv; g_gate[token][1] = e1 * inv;
        atomicAdd(&g_count[i0], 1);
        atomicAdd(&g_count[i1], 1);
    }

    // ---- last block performs the tiny exclusive scan (replaces scan_kernel) ----
    __syncthreads();
    if (tid == 0) {
        __threadfence();
        int ticket = atomicAdd(&g_done, 1);
        if (ticket == (int)gridDim.x - 1) {
            int acc2 = 0;
            for (int e = 0; e < NE; e++) {
                g_offs[e] = acc2; g_cursor[e] = acc2; acc2 += g_count[e];
            }
            g_done = 0;                 // reset for next replay
        }
    }
}

// ---------------- 3: slot assignment (block-aggregated atomics) ----------------
__global__ void assign_kernel() {
    __shared__ int loc[NE], bbase[NE];
    int tid = threadIdx.x;
    if (tid < NE) loc[tid] = 0;
    __syncthreads();
    int n = blockIdx.x * 256 + tid;
    int e[TOPK], p[TOPK];
#pragma unroll
    for (int k = 0; k < TOPK; k++) {
        e[k] = g_eidx[n][k];
        p[k] = atomicAdd(&loc[e[k]], 1);
    }
    __syncthreads();
    if (tid < NE) bbase[tid] = atomicAdd(&g_cursor[tid], loc[tid]);
    __syncthreads();
#pragma unroll
    for (int k = 0; k < TOPK; k++) {
        int pos = bbase[e[k]] + p[k];
        g_tok[pos]   = n;
        g_slot[n][k] = pos;
    }
}

// ---------------- 4: grouped expert GEMM, tf32 mma.sync, smem double-buffer ----------------
// CTA tile 128x128, k-tile 32, warps 2x4 (warp tile 64x32). Operands pre-converted tf32
// bits; both tiles [128 rows][32 k-words], row stride 36 words (conflict-free frag LDS).
// LDG->regs prefetch for tile kt+1 overlaps compute of kt; ONE __syncthreads per tile.
#define KTILE    32
#define LDW      36
#define ROW_B    (LDW * 4)              // 144 bytes
#define AB_BYTES (128 * ROW_B)          // 18432 per operand
#define BUF_B    (2 * AB_BYTES)         // 36864 per buffer (A ++ B)
#define DYN_SMEM (2 * BUF_B)            // 73728

__global__ void __launch_bounds__(256, 2)
expert_gemm() {
    const int e   = blockIdx.z;
    const int cnt = g_count[e];
    const int m0  = blockIdx.y * 128;
    if (m0 >= cnt) return;
    const int n0   = blockIdx.x * 128;
    const int base = g_offs[e];

    extern __shared__ __align__(16) char dyn[];

    const int tid  = threadIdx.x;   // 256
    const int lane = tid & 31;
    const int wid  = tid >> 5;
    const int wm   = (wid & 1) * 64;
    const int wn   = (wid >> 1) * 32;
    const int gr   = lane >> 2;
    const int gc   = lane & 3;

    // ---- load mapping: row = tid>>1 (0..127), 4 x uint4 chunks at (tid&1)*4 ----
    const int row = tid >> 1;
    const int cq  = (tid & 1) * 4;                 // uint4 index within 8-chunk row
    int rr = m0 + row; if (rr >= cnt) rr = cnt - 1;       // clamp; rows >= cnt never stored
    const uint4* arow = (const uint4*)(g_xt + (size_t)g_tok[base + rr] * DM) + cq;
    const uint4* brow = (const uint4*)(g_wt + ((size_t)e * DM + n0 + row) * DM) + cq;
    char* const sdstA = dyn + row * ROW_B + cq * 16;      // + buf*BUF_B
    char* const sdstB = sdstA + AB_BYTES;

    float acc[4][4][4];
#pragma unroll
    for (int mi = 0; mi < 4; mi++)
#pragma unroll
        for (int ni = 0; ni < 4; ni++)
#pragma unroll
            for (int q = 0; q < 4; q++) acc[mi][ni][q] = 0.f;

    uint4 av[4], bv[4];
    // ---- prologue: tile 0 -> buffer 0 ----
#pragma unroll
    for (int j = 0; j < 4; j++) av[j] = arow[j];
#pragma unroll
    for (int j = 0; j < 4; j++) bv[j] = brow[j];
#pragma unroll
    for (int j = 0; j < 4; j++) *(uint4*)(sdstA + j * 16) = av[j];
#pragma unroll
    for (int j = 0; j < 4; j++) *(uint4*)(sdstB + j * 16) = bv[j];
    __syncthreads();

    const int NKT = DM / KTILE;     // 16
    for (int kt = 0; kt < NKT; kt++) {
        // ---- prefetch tile kt+1 into registers (overlaps with mma below) ----
        const bool has_next = (kt + 1) < NKT;
        if (has_next) {
            const int o = (kt + 1) * (KTILE / 4);  // uint4 offset
#pragma unroll
            for (int j = 0; j < 4; j++) av[j] = arow[o + j];
#pragma unroll
            for (int j = 0; j < 4; j++) bv[j] = brow[o + j];
        }

        // ---- compute tile kt from buffer kt&1 ----
        const unsigned* Ab = (const unsigned*)(dyn + (kt & 1) * BUF_B);
        const unsigned* Bb = (const unsigned*)(dyn + (kt & 1) * BUF_B + AB_BYTES);
#pragma unroll
        for (int s = 0; s < 4; s++) {
            const int kb = s * 8;
            unsigned a[4][4], b[4][2];
#pragma unroll
            for (int mi = 0; mi < 4; mi++) {
                const unsigned* r0 = Ab + (wm + mi * 16 + gr) * LDW;
                const unsigned* r1 = r0 + 8 * LDW;
                a[mi][0] = r0[kb + gc];
                a[mi][1] = r1[kb + gc];
                a[mi][2] = r0[kb + gc + 4];
                a[mi][3] = r1[kb + gc + 4];
            }
#pragma unroll
            for (int ni = 0; ni < 4; ni++) {
                const unsigned* rb = Bb + (wn + ni * 8 + gr) * LDW;
                b[ni][0] = rb[kb + gc];
                b[ni][1] = rb[kb + gc + 4];
            }
#pragma unroll
            for (int mi = 0; mi < 4; mi++)
#pragma unroll
                for (int ni = 0; ni < 4; ni++)
                    mma_tf32(acc[mi][ni], a[mi], b[ni]);
        }

        // ---- commit prefetched tile to buffer (kt+1)&1; single barrier ----
        if (has_next) {
            char* dA = sdstA + ((kt + 1) & 1) * BUF_B;
            char* dB = sdstB + ((kt + 1) & 1) * BUF_B;
#pragma unroll
            for (int j = 0; j < 4; j++) *(uint4*)(dA + j * 16) = av[j];
#pragma unroll
            for (int j = 0; j < 4; j++) *(uint4*)(dB + j * 16) = bv[j];
            __syncthreads();
        }
    }

    // ---- epilogue: d0/d1 -> (row, 2c), d2/d3 -> (row+8, 2c) ----
#pragma unroll
    for (int mi = 0; mi < 4; mi++) {
        int r0 = m0 + wm + mi * 16 + gr;
        int r1 = r0 + 8;
#pragma unroll
        for (int ni = 0; ni < 4; ni++) {
            int c = n0 + wn + ni * 8 + 2 * gc;
            if (r0 < cnt)
                *(float2*)(g_y + (size_t)(base + r0) * DM + c) =
                    make_float2(acc[mi][ni][0], acc[mi][ni][1]);
            if (r1 < cnt)
                *(float2*)(g_y + (size_t)(base + r1) * DM + c) =
                    make_float2(acc[mi][ni][2], acc[mi][ni][3]);
        }
    }
}

// ---------------- 5: combine + fused balance loss (extra block) ----------------
__device__ __forceinline__ float comb1(float g0, float g1, float ya, float yb) {
    float c = g0 * __expf(ya) + g1 * __expf(yb);
    if (c == 0.f) c = 2.220446049250313e-16f;
    return __logf(c);
}
__global__ void combine_kernel(float* __restrict__ out, int out_size) {
    if (blockIdx.x == gridDim.x - 1) {
        // ---- balance loss (deterministic reduction), one block ----
        __shared__ float s[NE][256];
        int tid = threadIdx.x;
        float imp[NE];
#pragma unroll
        for (int e = 0; e < NE; e++) imp[e] = 0.f;
        for (int n = tid; n < NTOK; n += 256) {
#pragma unroll
            for (int k = 0; k < TOPK; k++)
                imp[g_eidx[n][k]] += g_gate[n][k];
        }
#pragma unroll
        for (int e = 0; e < NE; e++) s[e][tid] = imp[e];
        __syncthreads();
        for (int st = 128; st > 0; st >>= 1) {
            if (tid < st) {
#pragma unroll
                for (int e = 0; e < NE; e++) s[e][tid] += s[e][tid + st];
            }
            __syncthreads();
        }
        if (tid == 0) {
            float mi = 0.f, ml = 0.f, iv[NE], lv[NE];
            for (int e = 0; e < NE; e++) {
                iv[e] = s[e][0]; lv[e] = (float)g_count[e];
                mi += iv[e]; ml += lv[e];
            }
            mi *= (1.f / NE); ml *= (1.f / NE);
            float vi = 0.f, vl = 0.f;
            for (int e = 0; e < NE; e++) {
                float di = iv[e] - mi, dl = lv[e] - ml;
                vi += di * di; vl += dl * dl;
            }
            vi *= (1.f / NE); vl *= (1.f / NE);
            float loss = vi / (mi * mi + 1e-10f) + vl / (ml * ml + 1e-10f);
            if (out_size > NTOK * DM) out[NTOK * DM] = loss;
        }
        return;
    }
    int idx = blockIdx.x * 256 + threadIdx.x;     // float4 granularity
    int n = idx >> 7, f = idx & 127;
    float g0 = g_gate[n][0], g1 = g_gate[n][1];
    const float4* y0 = (const float4*)(g_y + (size_t)g_slot[n][0] * DM);
    const float4* y1 = (const float4*)(g_y + (size_t)g_slot[n][1] * DM);
    float4 a = y0[f], b = y1[f];
    float4 rv;
    rv.x = comb1(g0, g1, a.x, b.x);
    rv.y = comb1(g0, g1, a.y, b.y);
    rv.z = comb1(g0, g1, a.z, b.z);
    rv.w = comb1(g0, g1, a.w, b.w);
    ((float4*)(out + (size_t)n * DM))[f] = rv;
}

// ---------------- launch ----------------
extern "C" void kernel_launch(void* const* d_in, const int* in_sizes, int n_in,
                              void* d_out, int out_size) {
    const float* x  = (const float*)d_in[0];   // [8192, 512]
    const float* wg = (const float*)d_in[1];   // [512, 8]
    const float* ew = (const float*)d_in[2];   // [8, 512, 512]
    float* out = (float*)d_out;

    static int attr_done = 0;
    if (!attr_done) {
        cudaFuncSetAttribute(expert_gemm, cudaFuncAttributeMaxDynamicSharedMemorySize, DYN_SMEM);
        attr_done = 1;
    }

    {
        dim3 g(DM / 32, DM / 32, NE);
        wtrans_kernel<<<g, dim3(32, 8)>>>(ew);      // W^T tf32 + counter reset
    }
    gate_kernel<<<NTOK / 8, 256>>>(x, wg);          // gates + g_xt + embedded scan
    assign_kernel<<<NTOK / 256, 256>>>();
    {
        dim3 grid(DM / 128, NTOK / 128, NE);
        expert_gemm<<<grid, 256, DYN_SMEM>>>();
    }
    combine_kernel<<<NTOK * (DM / 4) / 256 + 1, 256>>>(out, out_size);
}